// round 17
// baseline (speedup 1.0000x reference)
#include <cuda_runtime.h>

#define NB 1024
#define NT 256
#define NS 16
#define NM 4
#define NSTEP 255
#define ROWF 20
#define CH 15            // chunk: 255 = 17 * 15
#define NCHUNK 17
#define CHF4 (CH * 100)  // float4 per chunk = 1500

// blob[t]: 100 float4 per step, float4-column-major:
//   f4 index (c*20 + row): row<16 state rows, row 16+m measurement rows.
__device__ float4 g_blob[NSTEP * 100];
__device__ float  g_s0[16];
__device__ float  g_y0[4];
__device__ int    g_ready;       // chunks published (monotonic within a launch)
__device__ int    g_conv_chunk;  // first chunk whose maps are all fixed-point

__global__ void reset_kernel() { g_ready = 0; g_conv_chunk = NCHUNK; }

// ---------------------------------------------------------------------------
// KF consumer step: lanes 0..15 new state, lanes 16..19 write output.
// ---------------------------------------------------------------------------
#define KF_STEP(Ab, ob, tt)                                                    \
    do {                                                                       \
        float acc0, acc1, res;                                                 \
        acc0 = (Ab)[0].x * __shfl_sync(0xffffffffu, x, 0);                     \
        acc1 = (Ab)[0].y * __shfl_sync(0xffffffffu, x, 1);                     \
        acc0 = fmaf((Ab)[0].z, __shfl_sync(0xffffffffu, x, 2), acc0);          \
        acc1 = fmaf((Ab)[0].w, __shfl_sync(0xffffffffu, x, 3), acc1);          \
        acc0 = fmaf((Ab)[1].x, __shfl_sync(0xffffffffu, x, 4), acc0);          \
        acc1 = fmaf((Ab)[1].y, __shfl_sync(0xffffffffu, x, 5), acc1);          \
        acc0 = fmaf((Ab)[1].z, __shfl_sync(0xffffffffu, x, 6), acc0);          \
        acc1 = fmaf((Ab)[1].w, __shfl_sync(0xffffffffu, x, 7), acc1);          \
        acc0 = fmaf((Ab)[2].x, __shfl_sync(0xffffffffu, x, 8), acc0);          \
        acc1 = fmaf((Ab)[2].y, __shfl_sync(0xffffffffu, x, 9), acc1);          \
        acc0 = fmaf((Ab)[2].z, __shfl_sync(0xffffffffu, x, 10), acc0);         \
        acc1 = fmaf((Ab)[2].w, __shfl_sync(0xffffffffu, x, 11), acc1);         \
        acc0 = fmaf((Ab)[3].x, __shfl_sync(0xffffffffu, x, 12), acc0);         \
        acc1 = fmaf((Ab)[3].y, __shfl_sync(0xffffffffu, x, 13), acc1);         \
        acc0 = fmaf((Ab)[3].z, __shfl_sync(0xffffffffu, x, 14), acc0);         \
        acc1 = fmaf((Ab)[3].w, __shfl_sync(0xffffffffu, x, 15), acc1);         \
        acc0 = fmaf((Ab)[4].x, (ob).x, acc0);                                  \
        acc1 = fmaf((Ab)[4].y, (ob).y, acc1);                                  \
        acc0 = fmaf((Ab)[4].z, (ob).z, acc0);                                  \
        acc1 = fmaf((Ab)[4].w, (ob).w, acc1);                                  \
        res = acc0 + acc1;                                                     \
        if (lane < 16) x = res;                                                \
        else if (lane < 20) op[((tt) + 1) * 4 + (lane - 16)] = res;            \
    } while (0)

__global__ __launch_bounds__(256, 1) void fused_kernel(
    const float* __restrict__ inp, float* __restrict__ out,
    const float* __restrict__ F, const float* __restrict__ H,
    const float* __restrict__ Q, const float* __restrict__ R,
    const float* __restrict__ x0, const float* __restrict__ sd)
{
    // producer shared state
    __shared__ __align__(16) float sP[16][ROWF];
    __shared__ __align__(16) float sA[16][ROWF];
    __shared__ __align__(16) float sF[16][ROWF];
    __shared__ __align__(16) float sQ[16][ROWF];
    __shared__ __align__(16) float sH[4][ROWF];
    __shared__ __align__(16) float sHPT[16][4];
    __shared__ __align__(16) float sK[16][4];
    __shared__ __align__(16) float sL[16][4];
    __shared__ __align__(16) float sSi[4][4];
    __shared__ __align__(16) float sR[4][4];
    __shared__ float ssd2[16], ss0[16];
    // consumer staging buffers
    __shared__ __align__(16) float4 sbuf[CHF4];   // 24 KB
    __shared__ __align__(16) float4 sobs[8][16];  // 15 used per warp
    __shared__ int sgo;

    const int tid = threadIdx.x;

    if (blockIdx.x == 0) {
        // ======== init with all 256 threads (proven code) ========
        {
            const int i0 = tid >> 4, j0 = tid & 15;
            sF[i0][j0] = F[i0 * 16 + j0];
            sQ[i0][j0] = Q[i0 * 16 + j0];
            if (i0 < 4) sH[i0][j0] = H[i0 * 16 + j0];
            if (tid < 16) {
                sR[tid >> 2][tid & 3] = R[tid];
                float v = sd[tid];
                ssd2[tid] = v * v;
            }
            __syncthreads();
            // P0 = F diag(sd^2) F^T + Q ; s0 = F x0 ; y0 = H s0
            {
                float a0 = sQ[i0][j0], a1 = 0.f, a2 = 0.f, a3 = 0.f;
#pragma unroll
                for (int k = 0; k < 16; k += 4) {
                    a0 = fmaf(sF[i0][k + 0] * ssd2[k + 0], sF[j0][k + 0], a0);
                    a1 = fmaf(sF[i0][k + 1] * ssd2[k + 1], sF[j0][k + 1], a1);
                    a2 = fmaf(sF[i0][k + 2] * ssd2[k + 2], sF[j0][k + 2], a2);
                    a3 = fmaf(sF[i0][k + 3] * ssd2[k + 3], sF[j0][k + 3], a3);
                }
                sP[i0][j0] = (a0 + a1) + (a2 + a3);
            }
            if (tid < 16) {
                float acc = 0.f;
#pragma unroll
                for (int k = 0; k < 16; k++) acc = fmaf(sF[tid][k], x0[k], acc);
                ss0[tid] = acc;
                g_s0[tid] = acc;
            }
            __syncthreads();
            if (tid < 4) {
                float acc = 0.f;
#pragma unroll
                for (int k = 0; k < 16; k++) acc = fmaf(sH[tid][k], ss0[k], acc);
                g_y0[tid] = acc;
            }
        }
        if (tid >= 32) return;   // warps 1-7 done; single-warp Riccati below

        // ======== SINGLE-WARP Joseph Riccati, no block barriers ========
        const int l = tid;
        const int i = l & 15;        // owned row
        const int hk = l >> 4;       // split-k half (0/1)
        const int kb = hk << 3;      // 0 or 8
        const int mS = i >> 2, nS = i & 3;

        float Freg[16], Hreg[4][16];
#pragma unroll
        for (int k = 0; k < 16; k++) Freg[k] = sF[i][k];
#pragma unroll
        for (int m = 0; m < 4; m++)
#pragma unroll
            for (int k = 0; k < 16; k++) Hreg[m][k] = sH[m][k];

        float* blob = (float*)g_blob;

#pragma unroll 1
        for (int t = 0; t < NSTEP; ++t) {
            float* base = blob + t * 400;

            // S1: hp[m] = sum_k H[m][k] * P[k][i]   (true column read)
            float hp0 = 0.f, hp1 = 0.f, hp2 = 0.f, hp3 = 0.f;
#pragma unroll
            for (int k = 0; k < 16; k++) {
                float p = sP[k][i];
                hp0 = fmaf(Hreg[0][k], p, hp0);
                hp1 = fmaf(Hreg[1][k], p, hp1);
                hp2 = fmaf(Hreg[2][k], p, hp2);
                hp3 = fmaf(Hreg[3][k], p, hp3);
            }
            if (l < 16) *(float4*)&sHPT[i][0] = make_float4(hp0, hp1, hp2, hp3);
            __syncwarp();

            // S2: sv = S[mS][nS] (split over j) ; all-shfl cofactor inverse
            float sv;
            {
                float pa = 0.f;
#pragma unroll
                for (int k = 0; k < 8; k++) {
                    int jj = kb + k;
                    pa = fmaf(sHPT[jj][mS], sH[nS][jj], pa);
                }
                pa += __shfl_xor_sync(0xffffffffu, pa, 16);
                sv = pa + sR[mS][nS];
            }
            {
                int r0 = 0 + (0 >= mS), r1 = 1 + (1 >= mS), r2 = 2 + (2 >= mS);
                int c0 = 0 + (0 >= nS), c1 = 1 + (1 >= nS), c2 = 2 + (2 >= nS);
                float a = __shfl_sync(0xffffffffu, sv, r0 * 4 + c0);
                float b = __shfl_sync(0xffffffffu, sv, r0 * 4 + c1);
                float c = __shfl_sync(0xffffffffu, sv, r0 * 4 + c2);
                float d = __shfl_sync(0xffffffffu, sv, r1 * 4 + c0);
                float e = __shfl_sync(0xffffffffu, sv, r1 * 4 + c1);
                float f = __shfl_sync(0xffffffffu, sv, r1 * 4 + c2);
                float g = __shfl_sync(0xffffffffu, sv, r2 * 4 + c0);
                float h = __shfl_sync(0xffffffffu, sv, r2 * 4 + c1);
                float i2 = __shfl_sync(0xffffffffu, sv, r2 * 4 + c2);
                float minor = a * (e * i2 - f * h) - b * (d * i2 - f * g) + c * (d * h - e * g);
                float cof = ((mS + nS) & 1) ? -minor : minor;
                float dv = sv * cof;
                dv += __shfl_xor_sync(0xffffffffu, dv, 1);
                dv += __shfl_xor_sync(0xffffffffu, dv, 2);
                float cofT = __shfl_sync(0xffffffffu, cof, nS * 4 + mS);
                float rdet = __fdividef(1.f, dv);
                if (l < 16) sSi[mS][nS] = cofT * rdet;
            }
            __syncwarp();

            // S3: Krow[m'] = sum_m hp[m] * Si[m][m']   (local)
            float K0, K1, K2, K3;
            {
                float4 s0 = *(const float4*)&sSi[0][0];
                float4 s1 = *(const float4*)&sSi[1][0];
                float4 s2 = *(const float4*)&sSi[2][0];
                float4 s3 = *(const float4*)&sSi[3][0];
                K0 = fmaf(hp0, s0.x, fmaf(hp1, s1.x, fmaf(hp2, s2.x, hp3 * s3.x)));
                K1 = fmaf(hp0, s0.y, fmaf(hp1, s1.y, fmaf(hp2, s2.y, hp3 * s3.y)));
                K2 = fmaf(hp0, s0.z, fmaf(hp1, s1.z, fmaf(hp2, s2.z, hp3 * s3.z)));
                K3 = fmaf(hp0, s0.w, fmaf(hp1, s1.w, fmaf(hp2, s2.w, hp3 * s3.w)));
            }
            if (l < 16) *(float4*)&sK[i][0] = make_float4(K0, K1, K2, K3);
            __syncwarp();

            // S4: Lrow = F*K ; LR = Lrow*R  (local dots over smem rows)
            float L0 = 0.f, L1 = 0.f, L2 = 0.f, L3 = 0.f;
#pragma unroll
            for (int k = 0; k < 16; k++) {
                float4 kk = *(const float4*)&sK[k][0];
                float fv = Freg[k];
                L0 = fmaf(fv, kk.x, L0);
                L1 = fmaf(fv, kk.y, L1);
                L2 = fmaf(fv, kk.z, L2);
                L3 = fmaf(fv, kk.w, L3);
            }
            float LR0, LR1, LR2, LR3;
            {
                float4 ra = *(const float4*)&sR[0][0];
                float4 rb = *(const float4*)&sR[1][0];
                float4 rc = *(const float4*)&sR[2][0];
                float4 rd = *(const float4*)&sR[3][0];
                LR0 = fmaf(L0, ra.x, fmaf(L1, rb.x, fmaf(L2, rc.x, L3 * rd.x)));
                LR1 = fmaf(L0, ra.y, fmaf(L1, rb.y, fmaf(L2, rc.y, L3 * rd.y)));
                LR2 = fmaf(L0, ra.z, fmaf(L1, rb.z, fmaf(L2, rc.z, L3 * rd.z)));
                LR3 = fmaf(L0, ra.w, fmaf(L1, rb.w, fmaf(L2, rc.w, L3 * rd.w)));
            }

            // S5: Arow = F - Lrow*H  (local); publish A,L to smem + blob
            float Arow[16];
#pragma unroll
            for (int jj = 0; jj < 16; jj++) {
                float aa = Freg[jj];
                aa = fmaf(-L0, Hreg[0][jj], aa);
                aa = fmaf(-L1, Hreg[1][jj], aa);
                aa = fmaf(-L2, Hreg[2][jj], aa);
                aa = fmaf(-L3, Hreg[3][jj], aa);
                Arow[jj] = aa;
            }
            if (l < 16) {
                *(float4*)&sA[i][0]  = make_float4(Arow[0], Arow[1], Arow[2], Arow[3]);
                *(float4*)&sA[i][4]  = make_float4(Arow[4], Arow[5], Arow[6], Arow[7]);
                *(float4*)&sA[i][8]  = make_float4(Arow[8], Arow[9], Arow[10], Arow[11]);
                *(float4*)&sA[i][12] = make_float4(Arow[12], Arow[13], Arow[14], Arow[15]);
                *(float4*)&sL[i][0]  = make_float4(L0, L1, L2, L3);
                *(float4*)(base + (0 * 20 + i) * 4) = make_float4(Arow[0], Arow[1], Arow[2], Arow[3]);
                *(float4*)(base + (1 * 20 + i) * 4) = make_float4(Arow[4], Arow[5], Arow[6], Arow[7]);
                *(float4*)(base + (2 * 20 + i) * 4) = make_float4(Arow[8], Arow[9], Arow[10], Arow[11]);
                *(float4*)(base + (3 * 20 + i) * 4) = make_float4(Arow[12], Arow[13], Arow[14], Arow[15]);
                *(float4*)(base + (4 * 20 + i) * 4) = make_float4(L0, L1, L2, L3);
            }
            __syncwarp();

            // S7: Trow[j] = sum_k Arow[k] * P[j][k]  (symmetric P; split-k)
            float Ah[8], Th[8];
#pragma unroll
            for (int k = 0; k < 8; k++) Ah[k] = hk ? Arow[8 + k] : Arow[k];
#pragma unroll
            for (int jj = 0; jj < 16; jj++) {
                const float* pr = &sP[jj][kb];
                float4 pA = *(const float4*)(pr);
                float4 pB = *(const float4*)(pr + 4);
                float tv = Ah[0] * pA.x;
                tv = fmaf(Ah[1], pA.y, tv);
                tv = fmaf(Ah[2], pA.z, tv);
                tv = fmaf(Ah[3], pA.w, tv);
                tv = fmaf(Ah[4], pB.x, tv);
                tv = fmaf(Ah[5], pB.y, tv);
                tv = fmaf(Ah[6], pB.z, tv);
                tv = fmaf(Ah[7], pB.w, tv);
                tv += __shfl_xor_sync(0xffffffffu, tv, 16);
                if ((jj >> 3) == hk) Th[jj & 7] = tv;   // keep own-half slice
            }

            // S8: P'[i][j] = sum_k Trow[k]*A[j][k] + LR*Lrow_j + Q  (split-k)
            int flag = 0;
#pragma unroll
            for (int jj = 0; jj < 16; jj++) {
                const float* ar = &sA[jj][kb];
                float4 aA = *(const float4*)(ar);
                float4 aB = *(const float4*)(ar + 4);
                float pv = Th[0] * aA.x;
                pv = fmaf(Th[1], aA.y, pv);
                pv = fmaf(Th[2], aA.z, pv);
                pv = fmaf(Th[3], aA.w, pv);
                pv = fmaf(Th[4], aB.x, pv);
                pv = fmaf(Th[5], aB.y, pv);
                pv = fmaf(Th[6], aB.z, pv);
                pv = fmaf(Th[7], aB.w, pv);
                if (hk == 0) {
                    float4 lj = *(const float4*)&sL[jj][0];
                    pv = fmaf(LR0, lj.x, pv);
                    pv = fmaf(LR1, lj.y, pv);
                    pv = fmaf(LR2, lj.z, pv);
                    pv = fmaf(LR3, lj.w, pv);
                    pv += sQ[i][jj];
                }
                pv += __shfl_xor_sync(0xffffffffu, pv, 16);
                float op2 = sP[i][jj];
                flag |= !(fabsf(pv - op2) <= 2e-3f * fabsf(pv) + 2e-4f);
                if (l < 16) sP[i][jj] = pv;
            }

            // S9: HA column i (local from sA); HB on lanes 0-15; blob stores
            float ha0 = 0.f, ha1 = 0.f, ha2 = 0.f, ha3 = 0.f;
#pragma unroll
            for (int k = 0; k < 16; k++) {
                float av = sA[k][i];
                ha0 = fmaf(Hreg[0][k], av, ha0);
                ha1 = fmaf(Hreg[1][k], av, ha1);
                ha2 = fmaf(Hreg[2][k], av, ha2);
                ha3 = fmaf(Hreg[3][k], av, ha3);
            }
            float hbv = 0.f;
            if (l < 16) {
#pragma unroll
                for (int k = 0; k < 16; k++)
                    hbv = fmaf(sH[mS][k], sL[k][nS], hbv);
                int cB = i >> 2, wB = i & 3;
                base[((cB) * 20 + 16 + 0) * 4 + wB] = ha0;
                base[((cB) * 20 + 16 + 1) * 4 + wB] = ha1;
                base[((cB) * 20 + 16 + 2) * 4 + wB] = ha2;
                base[((cB) * 20 + 16 + 3) * 4 + wB] = ha3;
                base[(4 * 20 + 16 + mS) * 4 + nS] = hbv;
            }
            int wflag = __any_sync(0xffffffffu, flag);
            __syncwarp();

            if (!wflag) {
                // converged: publish marker first, replicate tail, release.
                if (l == 0) {
                    __threadfence();
                    *(volatile int*)&g_conv_chunk = (t + CH) / CH;
                }
#pragma unroll 1
                for (int t2 = t + 1; t2 < NSTEP; ++t2) {
                    if (l < 16) {
                        float* b2 = blob + t2 * 400;
                        *(float4*)(b2 + (0 * 20 + i) * 4) = make_float4(Arow[0], Arow[1], Arow[2], Arow[3]);
                        *(float4*)(b2 + (1 * 20 + i) * 4) = make_float4(Arow[4], Arow[5], Arow[6], Arow[7]);
                        *(float4*)(b2 + (2 * 20 + i) * 4) = make_float4(Arow[8], Arow[9], Arow[10], Arow[11]);
                        *(float4*)(b2 + (3 * 20 + i) * 4) = make_float4(Arow[12], Arow[13], Arow[14], Arow[15]);
                        *(float4*)(b2 + (4 * 20 + i) * 4) = make_float4(L0, L1, L2, L3);
                        int cB = i >> 2, wB = i & 3;
                        b2[((cB) * 20 + 16 + 0) * 4 + wB] = ha0;
                        b2[((cB) * 20 + 16 + 1) * 4 + wB] = ha1;
                        b2[((cB) * 20 + 16 + 2) * 4 + wB] = ha2;
                        b2[((cB) * 20 + 16 + 3) * 4 + wB] = ha3;
                        b2[(4 * 20 + 16 + mS) * 4 + nS] = hbv;
                    }
                }
                if (l == 0) {
                    __threadfence();
                    *(volatile int*)&g_ready = NCHUNK;
                }
                return;
            }
            if (((t + 1) % CH) == 0 && l == 0) {
                __threadfence();
                *(volatile int*)&g_ready = (t + 1) / CH;
            }
        }
        return;
    }

    // ==================== CONSUMERS: warp-per-batch scan =====================
    const int lane = tid & 31;
    const int wrp = tid >> 5;
    const int b = ((blockIdx.x - 1) << 3) + wrp;
    const int g = (lane < 20) ? lane : 0;

    // wait for chunk 0 (also guarantees g_s0/g_y0 visible)
    if (tid == 0) {
        while (*(volatile int*)&g_ready < 1) __nanosleep(100);
        __threadfence();
    }
    __syncthreads();

    float x = (lane < 16) ? g_s0[lane] : 0.f;
    float* op = out + b * (NT * NM);
    const float* ip = inp + b * (NT * NM);
    if (lane >= 16 && lane < 20) op[lane - 16] = g_y0[lane - 16];

    const float4* gb = g_blob;
    const int bb = (blockIdx.x - 1) << 3;

    float4 A[5];     // persists across chunks: holds last step's map
    int t = 0;

#pragma unroll 1
    for (int c = 0; c < NCHUNK; ++c) {
        if (c > 0) {
            // block-uniform decision: stage chunk c, or switch to the
            // constant-map fast path (maps fixed from chunk g_conv_chunk on).
            if (tid == 0) {
                int go = 0;
                for (;;) {
                    if (*(volatile int*)&g_conv_chunk <= c) { go = 1; break; }
                    if (*(volatile int*)&g_ready >= c + 1) break;
                    __nanosleep(100);
                }
                __threadfence();
                sgo = go;
            }
            __syncthreads();
            if (sgo) break;   // uniform exit -> fast path; A = fixed map
        }
        // stage chunk c blob + this block's obs into shared
#pragma unroll
        for (int r = 0; r < 6; r++) {
            int idx = tid + r * 256;
            if (idx < CHF4) sbuf[idx] = gb[c * CHF4 + idx];
        }
        if (tid < 8 * CH) {
            int w2 = tid / CH, s = tid - w2 * CH;
            int tt = c * CH + s;   // <= 254
            sobs[w2][s] = *(const float4*)(inp + ((bb + w2) * NT + tt) * 4);
        }
        __syncthreads();

        const float4* s4 = sbuf;
#pragma unroll 1
        for (int s = 0; s < CH; ++s, ++t) {
#pragma unroll
            for (int cc = 0; cc < 5; cc++) A[cc] = s4[s * 100 + cc * 20 + g];
            float4 ob = sobs[wrp][s];
            KF_STEP(A, ob, t);
        }
        __syncthreads();  // all readers done before next chunk overwrites
    }

    // ---- constant-map fast path: barrier-free, obs prefetched 3 deep ----
    if (t < NSTEP) {
        float4 o0 = *(const float4*)(ip + t * 4);
        float4 o1 = (t + 1 < NSTEP) ? *(const float4*)(ip + (t + 1) * 4) : o0;
        float4 o2 = (t + 2 < NSTEP) ? *(const float4*)(ip + (t + 2) * 4) : o0;
#pragma unroll 3
        for (; t < NSTEP; ++t) {
            int tn = (t + 3 < NSTEP) ? t + 3 : t;
            float4 on = *(const float4*)(ip + tn * 4);
            KF_STEP(A, o0, t);
            o0 = o1; o1 = o2; o2 = on;
        }
    }
}

extern "C" void kernel_launch(void* const* d_in, const int* in_sizes, int n_in,
                              void* d_out, int out_size) {
    const float* inp = (const float*)d_in[0];
    const float* F   = (const float*)d_in[1];
    const float* H   = (const float*)d_in[2];
    const float* Q   = (const float*)d_in[3];
    const float* R   = (const float*)d_in[4];
    const float* x0  = (const float*)d_in[5];
    const float* sd  = (const float*)d_in[6];
    float* out = (float*)d_out;

    reset_kernel<<<1, 1>>>();
    fused_kernel<<<129, 256>>>(inp, out, F, H, Q, R, x0, sd);
}